// round 4
// baseline (speedup 1.0000x reference)
#include <cuda_runtime.h>
#include <cstdint>

// Problem dims
#define LL 16
#define TT 2048
#define DD 2048
#define RR 128
#define KK 1024   // tokens routed to s2 (top-k); TT-KK tokens need the s1 GEMM

// ---------------- scratch (device globals: no allocation allowed) ----------------
__device__ float g_hrelu[(size_t)LL * TT * RR];   // 16.8 MB
__device__ float g_logits[LL * TT];
__device__ int   g_copy_idx[LL * KK];             // top-K token ids per layer (output = s2 row)
__device__ int   g_comp_idx[LL * KK];             // remaining token ids (output = s1 row)

// ---------------- packed f32x2 helpers (2x fp32 FMA throughput on sm_103a) -------
__device__ __forceinline__ unsigned long long pack2(float lo, float hi) {
    unsigned long long r;
    asm("mov.b64 %0, {%1, %2};" : "=l"(r) : "f"(lo), "f"(hi));
    return r;
}
__device__ __forceinline__ void unpack2(unsigned long long v, float& lo, float& hi) {
    asm("mov.b64 {%0, %1}, %2;" : "=f"(lo), "=f"(hi) : "l"(v));
}
__device__ __forceinline__ unsigned long long fma2(unsigned long long a,
                                                   unsigned long long b,
                                                   unsigned long long c) {
    unsigned long long d;
    asm("fma.rn.f32x2 %0, %1, %2, %3;" : "=l"(d) : "l"(a), "l"(b), "l"(c));
    return d;
}

// =================================================================================
// Shared GEMM tile geometry: BM=128, BN=128, BK=16, 256 threads, 8x8 per thread.
//   A slab loads: 512 float4 (128 rows x 16 k), 2 per thread, stored transposed
//   B slab loads: 512 float4 (16 k x 128 n),   2 per thread
// Register prefetch: next slab's 4 float4 loaded right after the post-store sync,
// consumed next iteration -> LDG latency hidden under the 16-k compute phase.
// =================================================================================

// ---------------------------------------------------------------------------------
// Kernel 1: router hidden GEMM: g_hrelu[l,t,r] = relu(hidden[l,t,:]@W_r1[l,:,r]+b_r1)
// grid (1, TT/128, LL)
// ---------------------------------------------------------------------------------
__global__ __launch_bounds__(256, 2)
void router_gemm_kernel(const float* __restrict__ hidden,
                        const float* __restrict__ W1,
                        const float* __restrict__ b1) {
    const int l  = blockIdx.z;
    const int mt = blockIdx.y;

    const float* A  = hidden + (size_t)l * TT * DD + (size_t)mt * 128 * DD;
    const float* Bp = W1 + (size_t)l * DD * RR;

    __shared__ float as[16][132];   // [k][m]
    __shared__ float bs[16][128];   // [k][n]

    const int tid   = threadIdx.x;
    const int a_row = tid >> 2;         // 0..63 (and +64)
    const int a_kq  = tid & 3;          // k quad
    const int b_k   = tid >> 5;         // 0..7 (and +8)
    const int b_c   = (tid & 31) << 2;  // col
    const int tx    = tid & 15;
    const int ty    = tid >> 4;
    const int m0    = ty * 8;
    const int n0    = tx * 8;

    unsigned long long acc[8][4];
#pragma unroll
    for (int i = 0; i < 8; i++)
#pragma unroll
        for (int j = 0; j < 4; j++) acc[i][j] = 0ULL;

    float4 pa0 = *(const float4*)(A + (size_t)a_row * DD + a_kq * 4);
    float4 pa1 = *(const float4*)(A + (size_t)(a_row + 64) * DD + a_kq * 4);
    float4 pb0 = *(const float4*)(Bp + (size_t)b_k * RR + b_c);
    float4 pb1 = *(const float4*)(Bp + (size_t)(b_k + 8) * RR + b_c);

    for (int kt = 0; kt < DD / 16; kt++) {
        __syncthreads();
        as[a_kq * 4 + 0][a_row]      = pa0.x;
        as[a_kq * 4 + 1][a_row]      = pa0.y;
        as[a_kq * 4 + 2][a_row]      = pa0.z;
        as[a_kq * 4 + 3][a_row]      = pa0.w;
        as[a_kq * 4 + 0][a_row + 64] = pa1.x;
        as[a_kq * 4 + 1][a_row + 64] = pa1.y;
        as[a_kq * 4 + 2][a_row + 64] = pa1.z;
        as[a_kq * 4 + 3][a_row + 64] = pa1.w;
        *(float4*)&bs[b_k][b_c]     = pb0;
        *(float4*)&bs[b_k + 8][b_c] = pb1;
        __syncthreads();
        if (kt + 1 < DD / 16) {
            const int kb = (kt + 1) * 16;
            pa0 = *(const float4*)(A + (size_t)a_row * DD + kb + a_kq * 4);
            pa1 = *(const float4*)(A + (size_t)(a_row + 64) * DD + kb + a_kq * 4);
            pb0 = *(const float4*)(Bp + (size_t)(kb + b_k) * RR + b_c);
            pb1 = *(const float4*)(Bp + (size_t)(kb + b_k + 8) * RR + b_c);
        }
#pragma unroll
        for (int k = 0; k < 16; k++) {
            float4 am0 = *(const float4*)&as[k][m0];
            float4 am1 = *(const float4*)&as[k][m0 + 4];
            float4 bn0 = *(const float4*)&bs[k][n0];
            float4 bn1 = *(const float4*)&bs[k][n0 + 4];
            unsigned long long bp[4] = { pack2(bn0.x, bn0.y), pack2(bn0.z, bn0.w),
                                         pack2(bn1.x, bn1.y), pack2(bn1.z, bn1.w) };
            float am[8] = { am0.x, am0.y, am0.z, am0.w, am1.x, am1.y, am1.z, am1.w };
#pragma unroll
            for (int i = 0; i < 8; i++) {
                unsigned long long ai = pack2(am[i], am[i]);
#pragma unroll
                for (int j = 0; j < 4; j++) acc[i][j] = fma2(ai, bp[j], acc[i][j]);
            }
        }
    }

    float bias[8];
#pragma unroll
    for (int j = 0; j < 8; j++) bias[j] = b1[l * RR + n0 + j];
#pragma unroll
    for (int i = 0; i < 8; i++) {
        float v[8];
#pragma unroll
        for (int j = 0; j < 4; j++) unpack2(acc[i][j], v[2 * j], v[2 * j + 1]);
        float4 o0, o1;
        o0.x = fmaxf(v[0] + bias[0], 0.f); o0.y = fmaxf(v[1] + bias[1], 0.f);
        o0.z = fmaxf(v[2] + bias[2], 0.f); o0.w = fmaxf(v[3] + bias[3], 0.f);
        o1.x = fmaxf(v[4] + bias[4], 0.f); o1.y = fmaxf(v[5] + bias[5], 0.f);
        o1.z = fmaxf(v[6] + bias[6], 0.f); o1.w = fmaxf(v[7] + bias[7], 0.f);
        float* dst = g_hrelu + ((size_t)l * TT + mt * 128 + m0 + i) * RR + n0;
        *(float4*)dst       = o0;
        *(float4*)(dst + 4) = o1;
    }
}

// ---------------------------------------------------------------------------------
// Kernel 2: logits[l,t] = hrelu[l,t,:] @ W_r2[l,:] + b_r2[l]   (warp per token)
// ---------------------------------------------------------------------------------
__global__ void logits_kernel(const float* __restrict__ W2, const float* __restrict__ b2) {
    const int gw   = (blockIdx.x * blockDim.x + threadIdx.x) >> 5;
    const int lane = threadIdx.x & 31;
    const int l = gw >> 11;      // /2048
    const int t = gw & 2047;
    const float* h = g_hrelu + ((size_t)l * TT + t) * RR;
    const float* w = W2 + l * RR;
    float s = 0.f;
#pragma unroll
    for (int r = 0; r < RR; r += 32) s += h[r + lane] * w[r + lane];
#pragma unroll
    for (int o = 16; o; o >>= 1) s += __shfl_xor_sync(0xffffffffu, s, o);
    if (lane == 0) g_logits[l * TT + t] = s + b2[l];
}

// ---------------------------------------------------------------------------------
// Kernel 3: exact top-K per layer via bitonic sort of (logit,idx) keys.
// sigmoid is monotone -> top-k on logits == top-k on probs. Ties break low-index
// first (matches jax.lax.top_k). One block of 1024 threads per layer.
// ---------------------------------------------------------------------------------
__global__ void topk_kernel() {
    __shared__ unsigned long long keys[2048];
    const int l = blockIdx.x;
    const int tid = threadIdx.x;
    for (int i = tid; i < 2048; i += 1024) {
        float f = g_logits[l * TT + i];
        unsigned u = __float_as_uint(f);
        u = (u & 0x80000000u) ? ~u : (u | 0x80000000u);           // order-preserving map
        keys[i] = ((unsigned long long)(~u) << 32) | (unsigned)i; // asc key = desc logit
    }
    __syncthreads();
    for (int ks = 2; ks <= 2048; ks <<= 1) {
        for (int j = ks >> 1; j > 0; j >>= 1) {
            for (int i = tid; i < 2048; i += 1024) {
                int ixj = i ^ j;
                if (ixj > i) {
                    unsigned long long a = keys[i], b = keys[ixj];
                    bool asc = ((i & ks) == 0);
                    if ((a > b) == asc) { keys[i] = b; keys[ixj] = a; }
                }
            }
            __syncthreads();
        }
    }
    for (int i = tid; i < 2048; i += 1024) {
        int idx = (int)(keys[i] & 0xFFFFFFFFu);
        if (i < KK) g_copy_idx[l * KK + i]        = idx;   // top-K -> s2 copy
        else        g_comp_idx[l * KK + (i - KK)] = idx;   // rest  -> s1 GEMM
    }
}

// ---------------------------------------------------------------------------------
// Kernel 4: out[l, t, :] = s2[l, t, :] for the top-K tokens (pure copy)
// ---------------------------------------------------------------------------------
__global__ void copy_s2_kernel(const float* __restrict__ s2, float* __restrict__ out) {
    const int l = blockIdx.y;
    const int t = g_copy_idx[l * KK + blockIdx.x];
    const float4* src = (const float4*)(s2  + ((size_t)l * TT + t) * DD);
    float4*       dst = (float4*)      (out + ((size_t)l * TT + t) * DD);
#pragma unroll
    for (int i = threadIdx.x; i < DD / 4; i += 256) dst[i] = src[i];
}

// ---------------------------------------------------------------------------------
// Kernel 5: s1 GEMM for the non-top-K rows only (half the tokens):
//   out[l, row, n] = hidden[l, row, :] @ W_s1[l, :, n] + b_s1[l, n]
// 128x128x16 tile, rows gathered via g_comp_idx. grid (DD/128, KK/128, LL)
// ---------------------------------------------------------------------------------
__global__ __launch_bounds__(256, 2)
void s1_gemm_kernel(const float* __restrict__ hidden,
                    const float* __restrict__ Ws1,
                    const float* __restrict__ bs1,
                    float* __restrict__ out) {
    const int l  = blockIdx.z;
    const int mt = blockIdx.y;   // 8 tiles of 128 gathered rows
    const int nt = blockIdx.x;   // 16 tiles of 128 output cols

    __shared__ float as[16][132];
    __shared__ float bs[16][128];
    __shared__ int   rows_s[128];

    const int tid = threadIdx.x;
    if (tid < 128) rows_s[tid] = g_comp_idx[l * KK + mt * 128 + tid];
    __syncthreads();

    const float* A  = hidden + (size_t)l * TT * DD;
    const float* Bp = Ws1 + (size_t)l * DD * DD + nt * 128;

    const int a_row = tid >> 2;
    const int a_kq  = tid & 3;
    const int b_k   = tid >> 5;
    const int b_c   = (tid & 31) << 2;
    const int tx    = tid & 15;
    const int ty    = tid >> 4;
    const int m0    = ty * 8;
    const int n0    = tx * 8;

    const int grow0 = rows_s[a_row];
    const int grow1 = rows_s[a_row + 64];

    unsigned long long acc[8][4];
#pragma unroll
    for (int i = 0; i < 8; i++)
#pragma unroll
        for (int j = 0; j < 4; j++) acc[i][j] = 0ULL;

    float4 pa0 = *(const float4*)(A + (size_t)grow0 * DD + a_kq * 4);
    float4 pa1 = *(const float4*)(A + (size_t)grow1 * DD + a_kq * 4);
    float4 pb0 = *(const float4*)(Bp + (size_t)b_k * DD + b_c);
    float4 pb1 = *(const float4*)(Bp + (size_t)(b_k + 8) * DD + b_c);

    for (int kt = 0; kt < DD / 16; kt++) {
        __syncthreads();
        as[a_kq * 4 + 0][a_row]      = pa0.x;
        as[a_kq * 4 + 1][a_row]      = pa0.y;
        as[a_kq * 4 + 2][a_row]      = pa0.z;
        as[a_kq * 4 + 3][a_row]      = pa0.w;
        as[a_kq * 4 + 0][a_row + 64] = pa1.x;
        as[a_kq * 4 + 1][a_row + 64] = pa1.y;
        as[a_kq * 4 + 2][a_row + 64] = pa1.z;
        as[a_kq * 4 + 3][a_row + 64] = pa1.w;
        *(float4*)&bs[b_k][b_c]     = pb0;
        *(float4*)&bs[b_k + 8][b_c] = pb1;
        __syncthreads();
        if (kt + 1 < DD / 16) {
            const int kb = (kt + 1) * 16;
            pa0 = *(const float4*)(A + (size_t)grow0 * DD + kb + a_kq * 4);
            pa1 = *(const float4*)(A + (size_t)grow1 * DD + kb + a_kq * 4);
            pb0 = *(const float4*)(Bp + (size_t)(kb + b_k) * DD + b_c);
            pb1 = *(const float4*)(Bp + (size_t)(kb + b_k + 8) * DD + b_c);
        }
#pragma unroll
        for (int k = 0; k < 16; k++) {
            float4 am0 = *(const float4*)&as[k][m0];
            float4 am1 = *(const float4*)&as[k][m0 + 4];
            float4 bn0 = *(const float4*)&bs[k][n0];
            float4 bn1 = *(const float4*)&bs[k][n0 + 4];
            unsigned long long bp[4] = { pack2(bn0.x, bn0.y), pack2(bn0.z, bn0.w),
                                         pack2(bn1.x, bn1.y), pack2(bn1.z, bn1.w) };
            float am[8] = { am0.x, am0.y, am0.z, am0.w, am1.x, am1.y, am1.z, am1.w };
#pragma unroll
            for (int i = 0; i < 8; i++) {
                unsigned long long ai = pack2(am[i], am[i]);
#pragma unroll
                for (int j = 0; j < 4; j++) acc[i][j] = fma2(ai, bp[j], acc[i][j]);
            }
        }
    }

    const int n0g = nt * 128 + n0;
    float bias[8];
#pragma unroll
    for (int j = 0; j < 8; j++) bias[j] = bs1[l * DD + n0g + j];
#pragma unroll
    for (int i = 0; i < 8; i++) {
        const int row = rows_s[m0 + i];
        float v[8];
#pragma unroll
        for (int j = 0; j < 4; j++) unpack2(acc[i][j], v[2 * j], v[2 * j + 1]);
        float4 o0, o1;
        o0.x = v[0] + bias[0]; o0.y = v[1] + bias[1];
        o0.z = v[2] + bias[2]; o0.w = v[3] + bias[3];
        o1.x = v[4] + bias[4]; o1.y = v[5] + bias[5];
        o1.z = v[6] + bias[6]; o1.w = v[7] + bias[7];
        float* dst = out + ((size_t)l * TT + row) * DD + n0g;
        *(float4*)dst       = o0;
        *(float4*)(dst + 4) = o1;
    }
}

// =================================================================================
extern "C" void kernel_launch(void* const* d_in, const int* in_sizes, int n_in,
                              void* d_out, int out_size) {
    const float* hidden = (const float*)d_in[0];
    const float* s2     = (const float*)d_in[1];
    const float* W_r1   = (const float*)d_in[2];
    const float* b_r1   = (const float*)d_in[3];
    const float* W_r2   = (const float*)d_in[4];
    const float* b_r2   = (const float*)d_in[5];
    const float* W_s1   = (const float*)d_in[6];
    const float* b_s1   = (const float*)d_in[7];
    float* out = (float*)d_out;

    dim3 g1(1, TT / 128, LL);
    router_gemm_kernel<<<g1, 256>>>(hidden, W_r1, b_r1);

    logits_kernel<<<(LL * TT) / 8, 256>>>(W_r2, b_r2);

    topk_kernel<<<LL, 1024>>>();

    copy_s2_kernel<<<dim3(KK, LL), 256>>>(s2, out);

    dim3 g2(DD / 128, KK / 128, LL);   // N tiles x M tiles x layers
    s1_gemm_kernel<<<g2, 256>>>(hidden, W_s1, b_s1, out);
}

// round 6
// speedup vs baseline: 1.7593x; 1.7593x over previous
#include <cuda_runtime.h>
#include <cuda_bf16.h>
#include <cstdint>

// Problem dims
#define LL 16
#define TT 2048
#define DD 2048
#define RR 128
#define KK 1024   // tokens routed to s2 (top-k); TT-KK tokens need the s1 GEMM

// ---------------- scratch (device globals: no allocation allowed) ----------------
__device__ float g_hrelu[(size_t)LL * TT * RR];
__device__ float g_logits[LL * TT];
__device__ int   g_copy_idx[LL * KK];
__device__ int   g_comp_idx[LL * KK];
// bf16 hi/lo split operands for the s1 GEMM (W transposed to [N,K])
__device__ __align__(1024) __nv_bfloat16 g_hid_hi[(size_t)LL * TT * DD];
__device__ __align__(1024) __nv_bfloat16 g_hid_lo[(size_t)LL * TT * DD];
__device__ __align__(1024) __nv_bfloat16 g_wt_hi[(size_t)LL * DD * DD];
__device__ __align__(1024) __nv_bfloat16 g_wt_lo[(size_t)LL * DD * DD];

// ---------------- helpers ----------------
__device__ __forceinline__ uint32_t smem_u32(const void* p) {
    uint32_t a;
    asm("{ .reg .u64 t; cvta.to.shared.u64 t, %1; cvt.u32.u64 %0, t; }" : "=r"(a) : "l"(p));
    return a;
}
__device__ __forceinline__ unsigned long long pack2(float lo, float hi) {
    unsigned long long r;
    asm("mov.b64 %0, {%1, %2};" : "=l"(r) : "f"(lo), "f"(hi));
    return r;
}
__device__ __forceinline__ void unpack2(unsigned long long v, float& lo, float& hi) {
    asm("mov.b64 {%0, %1}, %2;" : "=f"(lo), "=f"(hi) : "l"(v));
}
__device__ __forceinline__ unsigned long long fma2(unsigned long long a,
                                                   unsigned long long b,
                                                   unsigned long long c) {
    unsigned long long d;
    asm("fma.rn.f32x2 %0, %1, %2, %3;" : "=l"(d) : "l"(a), "l"(b), "l"(c));
    return d;
}
__device__ __forceinline__ void cp16(uint32_t s, const void* g) {
    asm volatile("cp.async.cg.shared.global [%0], [%1], 16;" :: "r"(s), "l"(g));
}
#define CP_COMMIT() asm volatile("cp.async.commit_group;" ::: "memory")
#define CP_WAIT(n)  asm volatile("cp.async.wait_group %0;" :: "n"(n) : "memory")

__device__ __forceinline__ void ldsm4(uint32_t* r, uint32_t addr) {
    asm volatile("ldmatrix.sync.aligned.m8n8.x4.shared.b16 {%0,%1,%2,%3}, [%4];"
                 : "=r"(r[0]), "=r"(r[1]), "=r"(r[2]), "=r"(r[3]) : "r"(addr));
}
__device__ __forceinline__ void mma_bf16(float* c, const uint32_t* a,
                                         uint32_t b0, uint32_t b1) {
    asm volatile(
        "mma.sync.aligned.m16n8k16.row.col.f32.bf16.bf16.f32 "
        "{%0,%1,%2,%3}, {%4,%5,%6,%7}, {%8,%9}, {%0,%1,%2,%3};"
        : "+f"(c[0]), "+f"(c[1]), "+f"(c[2]), "+f"(c[3])
        : "r"(a[0]), "r"(a[1]), "r"(a[2]), "r"(a[3]), "r"(b0), "r"(b1));
}

// =================================================================================
// Conversion kernels
// =================================================================================
__global__ __launch_bounds__(256) void conv_hidden_kernel(const float* __restrict__ hidden) {
    size_t i = ((size_t)blockIdx.x * 256 + threadIdx.x) * 4;
    float4 v = *(const float4*)(hidden + i);
    __nv_bfloat16 h0 = __float2bfloat16_rn(v.x), h1 = __float2bfloat16_rn(v.y);
    __nv_bfloat16 h2 = __float2bfloat16_rn(v.z), h3 = __float2bfloat16_rn(v.w);
    __nv_bfloat16 l0 = __float2bfloat16_rn(v.x - __bfloat162float(h0));
    __nv_bfloat16 l1 = __float2bfloat16_rn(v.y - __bfloat162float(h1));
    __nv_bfloat16 l2 = __float2bfloat16_rn(v.z - __bfloat162float(h2));
    __nv_bfloat16 l3 = __float2bfloat16_rn(v.w - __bfloat162float(h3));
    __nv_bfloat162 hp0(h0, h1), hp1(h2, h3), lp0(l0, l1), lp1(l2, l3);
    uint2 hw, lw;
    hw.x = *(uint32_t*)&hp0; hw.y = *(uint32_t*)&hp1;
    lw.x = *(uint32_t*)&lp0; lw.y = *(uint32_t*)&lp1;
    *(uint2*)(g_hid_hi + i) = hw;
    *(uint2*)(g_hid_lo + i) = lw;
}

// W_s1 [l, k, n] fp32 -> transposed bf16 hi/lo [l, n, k]
__global__ __launch_bounds__(256) void conv_wt_kernel(const float* __restrict__ Ws1) {
    __shared__ float tile[32][33];
    const int l  = blockIdx.z;
    const int kb = blockIdx.y * 32;
    const int nb = blockIdx.x * 32;
    const int x  = threadIdx.x;
    const int ty = threadIdx.y;
    const float* src = Ws1 + (size_t)l * DD * DD;
#pragma unroll
    for (int j = ty; j < 32; j += 8)
        tile[j][x] = src[(size_t)(kb + j) * DD + nb + x];
    __syncthreads();
#pragma unroll
    for (int j = ty; j < 32; j += 8) {
        float v = tile[x][j];   // = W[kb+x, nb+j]
        __nv_bfloat16 hi = __float2bfloat16_rn(v);
        __nv_bfloat16 lo = __float2bfloat16_rn(v - __bfloat162float(hi));
        size_t o = (size_t)l * DD * DD + (size_t)(nb + j) * DD + kb + x;
        g_wt_hi[o] = hi;
        g_wt_lo[o] = lo;
    }
}

// =================================================================================
// Router hidden GEMM (fp32 f32x2 — topk ordering must match reference)
// =================================================================================
__global__ __launch_bounds__(256, 2)
void router_gemm_kernel(const float* __restrict__ hidden,
                        const float* __restrict__ W1,
                        const float* __restrict__ b1) {
    const int l  = blockIdx.z;
    const int mt = blockIdx.y;

    const float* A  = hidden + (size_t)l * TT * DD + (size_t)mt * 128 * DD;
    const float* Bp = W1 + (size_t)l * DD * RR;

    __shared__ float as[16][132];
    __shared__ float bs[16][128];

    const int tid   = threadIdx.x;
    const int a_row = tid >> 2;
    const int a_kq  = tid & 3;
    const int b_k   = tid >> 5;
    const int b_c   = (tid & 31) << 2;
    const int tx    = tid & 15;
    const int ty    = tid >> 4;
    const int m0    = ty * 8;
    const int n0    = tx * 8;

    unsigned long long acc[8][4];
#pragma unroll
    for (int i = 0; i < 8; i++)
#pragma unroll
        for (int j = 0; j < 4; j++) acc[i][j] = 0ULL;

    float4 pa0 = *(const float4*)(A + (size_t)a_row * DD + a_kq * 4);
    float4 pa1 = *(const float4*)(A + (size_t)(a_row + 64) * DD + a_kq * 4);
    float4 pb0 = *(const float4*)(Bp + (size_t)b_k * RR + b_c);
    float4 pb1 = *(const float4*)(Bp + (size_t)(b_k + 8) * RR + b_c);

    for (int kt = 0; kt < DD / 16; kt++) {
        __syncthreads();
        as[a_kq * 4 + 0][a_row]      = pa0.x;
        as[a_kq * 4 + 1][a_row]      = pa0.y;
        as[a_kq * 4 + 2][a_row]      = pa0.z;
        as[a_kq * 4 + 3][a_row]      = pa0.w;
        as[a_kq * 4 + 0][a_row + 64] = pa1.x;
        as[a_kq * 4 + 1][a_row + 64] = pa1.y;
        as[a_kq * 4 + 2][a_row + 64] = pa1.z;
        as[a_kq * 4 + 3][a_row + 64] = pa1.w;
        *(float4*)&bs[b_k][b_c]     = pb0;
        *(float4*)&bs[b_k + 8][b_c] = pb1;
        __syncthreads();
        if (kt + 1 < DD / 16) {
            const int kb = (kt + 1) * 16;
            pa0 = *(const float4*)(A + (size_t)a_row * DD + kb + a_kq * 4);
            pa1 = *(const float4*)(A + (size_t)(a_row + 64) * DD + kb + a_kq * 4);
            pb0 = *(const float4*)(Bp + (size_t)(kb + b_k) * RR + b_c);
            pb1 = *(const float4*)(Bp + (size_t)(kb + b_k + 8) * RR + b_c);
        }
#pragma unroll
        for (int k = 0; k < 16; k++) {
            float4 am0 = *(const float4*)&as[k][m0];
            float4 am1 = *(const float4*)&as[k][m0 + 4];
            float4 bn0 = *(const float4*)&bs[k][n0];
            float4 bn1 = *(const float4*)&bs[k][n0 + 4];
            unsigned long long bp[4] = { pack2(bn0.x, bn0.y), pack2(bn0.z, bn0.w),
                                         pack2(bn1.x, bn1.y), pack2(bn1.z, bn1.w) };
            float am[8] = { am0.x, am0.y, am0.z, am0.w, am1.x, am1.y, am1.z, am1.w };
#pragma unroll
            for (int i = 0; i < 8; i++) {
                unsigned long long ai = pack2(am[i], am[i]);
#pragma unroll
                for (int j = 0; j < 4; j++) acc[i][j] = fma2(ai, bp[j], acc[i][j]);
            }
        }
    }

    float bias[8];
#pragma unroll
    for (int j = 0; j < 8; j++) bias[j] = b1[l * RR + n0 + j];
#pragma unroll
    for (int i = 0; i < 8; i++) {
        float v[8];
#pragma unroll
        for (int j = 0; j < 4; j++) unpack2(acc[i][j], v[2 * j], v[2 * j + 1]);
        float4 o0, o1;
        o0.x = fmaxf(v[0] + bias[0], 0.f); o0.y = fmaxf(v[1] + bias[1], 0.f);
        o0.z = fmaxf(v[2] + bias[2], 0.f); o0.w = fmaxf(v[3] + bias[3], 0.f);
        o1.x = fmaxf(v[4] + bias[4], 0.f); o1.y = fmaxf(v[5] + bias[5], 0.f);
        o1.z = fmaxf(v[6] + bias[6], 0.f); o1.w = fmaxf(v[7] + bias[7], 0.f);
        float* dst = g_hrelu + ((size_t)l * TT + mt * 128 + m0 + i) * RR + n0;
        *(float4*)dst       = o0;
        *(float4*)(dst + 4) = o1;
    }
}

// =================================================================================
// logits / topk / copy
// =================================================================================
__global__ void logits_kernel(const float* __restrict__ W2, const float* __restrict__ b2) {
    const int gw   = (blockIdx.x * blockDim.x + threadIdx.x) >> 5;
    const int lane = threadIdx.x & 31;
    const int l = gw >> 11;
    const int t = gw & 2047;
    const float* h = g_hrelu + ((size_t)l * TT + t) * RR;
    const float* w = W2 + l * RR;
    float s = 0.f;
#pragma unroll
    for (int r = 0; r < RR; r += 32) s += h[r + lane] * w[r + lane];
#pragma unroll
    for (int o = 16; o; o >>= 1) s += __shfl_xor_sync(0xffffffffu, s, o);
    if (lane == 0) g_logits[l * TT + t] = s + b2[l];
}

__global__ void topk_kernel() {
    __shared__ unsigned long long keys[2048];
    const int l = blockIdx.x;
    const int tid = threadIdx.x;
    for (int i = tid; i < 2048; i += 1024) {
        float f = g_logits[l * TT + i];
        unsigned u = __float_as_uint(f);
        u = (u & 0x80000000u) ? ~u : (u | 0x80000000u);
        keys[i] = ((unsigned long long)(~u) << 32) | (unsigned)i;
    }
    __syncthreads();
    for (int ks = 2; ks <= 2048; ks <<= 1) {
        for (int j = ks >> 1; j > 0; j >>= 1) {
            for (int i = tid; i < 2048; i += 1024) {
                int ixj = i ^ j;
                if (ixj > i) {
                    unsigned long long a = keys[i], b = keys[ixj];
                    bool asc = ((i & ks) == 0);
                    if ((a > b) == asc) { keys[i] = b; keys[ixj] = a; }
                }
            }
            __syncthreads();
        }
    }
    for (int i = tid; i < 2048; i += 1024) {
        int idx = (int)(keys[i] & 0xFFFFFFFFu);
        if (i < KK) g_copy_idx[l * KK + i]        = idx;
        else        g_comp_idx[l * KK + (i - KK)] = idx;
    }
}

__global__ void copy_s2_kernel(const float* __restrict__ s2, float* __restrict__ out) {
    const int l = blockIdx.y;
    const int t = g_copy_idx[l * KK + blockIdx.x];
    const float4* src = (const float4*)(s2  + ((size_t)l * TT + t) * DD);
    float4*       dst = (float4*)      (out + ((size_t)l * TT + t) * DD);
#pragma unroll
    for (int i = threadIdx.x; i < DD / 4; i += 256) dst[i] = src[i];
}

// =================================================================================
// s1 GEMM via mma.sync bf16 hi/lo 3-pass.
// CTA tile 128(M gathered rows) x 128(N), BK=32, 8 warps (2M x 4N), warp 64x32.
// SMEM rows padded to 80B -> ldmatrix conflict-free. cp.async double buffer.
// grid (DD/128=16, KK/128=8, LL=16), 256 threads.
// =================================================================================
#define ROWB   80
#define MATB   (128 * ROWB)      // 10240 B per matrix
#define STAGEB (4 * MATB)        // A_hi, A_lo, B_hi, B_lo
#define S1_SMEM (1024 + 2 * STAGEB)   // 82944 B

__global__ __launch_bounds__(256, 1)
void s1_mma_kernel(const float* __restrict__ bs1, float* __restrict__ out) {
    extern __shared__ __align__(128) char smem[];
    const uint32_t sb = smem_u32(smem);
    int* rows_s = (int*)smem;
    const int tid  = threadIdx.x;
    const int lane = tid & 31;
    const int wid  = tid >> 5;
    const int nt = blockIdx.x, mt = blockIdx.y, l = blockIdx.z;

    if (tid < 128) rows_s[tid] = g_comp_idx[l * KK + mt * 128 + tid];
    __syncthreads();

    // ---- cp.async source pointers: 2 chunks/thread/matrix ----
    const __nv_bfloat16 *pa_hi[2], *pa_lo[2], *pb_hi[2], *pb_lo[2];
    uint32_t sdst[2];
#pragma unroll
    for (int q = 0; q < 2; q++) {
        const int c   = tid + q * 256;       // 0..511
        const int row = c >> 2, ch = c & 3;  // row 0..127, 16B chunk 0..3
        const size_t aoff = ((size_t)l * TT + rows_s[row]) * DD + ch * 8;
        pa_hi[q] = g_hid_hi + aoff;
        pa_lo[q] = g_hid_lo + aoff;
        const size_t boff = ((size_t)l * DD + nt * 128 + row) * DD + ch * 8;
        pb_hi[q] = g_wt_hi + boff;
        pb_lo[q] = g_wt_lo + boff;
        sdst[q] = (uint32_t)(row * ROWB + ch * 16);
    }

    auto load_stage = [&](int buf, int it) {
        const uint32_t base = sb + 1024 + buf * STAGEB;
        const int ko = it * 32;
#pragma unroll
        for (int q = 0; q < 2; q++) {
            cp16(base + 0 * MATB + sdst[q], pa_hi[q] + ko);
            cp16(base + 1 * MATB + sdst[q], pa_lo[q] + ko);
            cp16(base + 2 * MATB + sdst[q], pb_hi[q] + ko);
            cp16(base + 3 * MATB + sdst[q], pb_lo[q] + ko);
        }
        CP_COMMIT();
    };

    // ---- ldmatrix per-lane offsets ----
    const int warp_m = wid & 1;   // 0..1
    const int warp_n = wid >> 1;  // 0..3
    // A frag (m16k16): row = warp_m*64 + mf*16 + (lane&15); +16B if lane>=16 (k8-15)
    const uint32_t offA = (uint32_t)((warp_m * 64 + (lane & 15)) * ROWB +
                                     ((lane & 16) ? 16 : 0));
    // B frag x4 (n16k16): row = warp_n*32 + nf2*16 + (lane&7) + ((lane&16)?8:0); +16B if lane&8
    const uint32_t offB = (uint32_t)((warp_n * 32 + (lane & 7) + ((lane & 16) ? 8 : 0)) * ROWB +
                                     ((lane & 8) ? 16 : 0));

    float acc[4][4][4];
#pragma unroll
    for (int i = 0; i < 4; i++)
#pragma unroll
        for (int j = 0; j < 4; j++)
#pragma unroll
            for (int k = 0; k < 4; k++) acc[i][j][k] = 0.f;

    load_stage(0, 0);

    const int NIT = DD / 32;   // 64
    for (int it = 0; it < NIT; it++) {
        const int buf = it & 1;
        if (it + 1 < NIT) { load_stage(buf ^ 1, it + 1); CP_WAIT(1); }
        else              { CP_WAIT(0); }
        __syncthreads();

        const uint32_t base = sb + 1024 + buf * STAGEB;
        const uint32_t Ah = base + 0 * MATB, Al = base + 1 * MATB;
        const uint32_t Bh = base + 2 * MATB, Bl = base + 3 * MATB;
#pragma unroll
        for (int kk = 0; kk < 2; kk++) {
            const uint32_t kof = kk * 32;
            uint32_t ah[4][4], al[4][4], bh[2][4], bl[2][4];
#pragma unroll
            for (int mf = 0; mf < 4; mf++) {
                const uint32_t o = offA + mf * 16 * ROWB + kof;
                ldsm4(ah[mf], Ah + o);
                ldsm4(al[mf], Al + o);
            }
#pragma unroll
            for (int nf2 = 0; nf2 < 2; nf2++) {
                const uint32_t o = offB + nf2 * 16 * ROWB + kof;
                ldsm4(bh[nf2], Bh + o);
                ldsm4(bl[nf2], Bl + o);
            }
#pragma unroll
            for (int mf = 0; mf < 4; mf++) {
#pragma unroll
                for (int nf = 0; nf < 4; nf++) {
                    const int n2 = nf >> 1, s = (nf & 1) * 2;
                    mma_bf16(acc[mf][nf], ah[mf], bh[n2][s], bh[n2][s + 1]);
                    mma_bf16(acc[mf][nf], ah[mf], bl[n2][s], bl[n2][s + 1]);
                    mma_bf16(acc[mf][nf], al[mf], bh[n2][s], bh[n2][s + 1]);
                }
            }
        }
        __syncthreads();
    }

    // ---- epilogue: +bias, scatter rows ----
    const int g   = lane >> 2;
    const int tig = lane & 3;
#pragma unroll
    for (int mf = 0; mf < 4; mf++) {
        const int m0 = warp_m * 64 + mf * 16 + g;
        const int r0 = rows_s[m0];
        const int r1 = rows_s[m0 + 8];
        float* d0 = out + ((size_t)l * TT + r0) * DD;
        float* d1 = out + ((size_t)l * TT + r1) * DD;
#pragma unroll
        for (int nf = 0; nf < 4; nf++) {
            const int n = nt * 128 + warp_n * 32 + nf * 8 + tig * 2;
            const float2 bv = *(const float2*)(bs1 + l * DD + n);
            float2 o0, o1;
            o0.x = acc[mf][nf][0] + bv.x; o0.y = acc[mf][nf][1] + bv.y;
            o1.x = acc[mf][nf][2] + bv.x; o1.y = acc[mf][nf][3] + bv.y;
            *(float2*)(d0 + n) = o0;
            *(float2*)(d1 + n) = o1;
        }
    }
}

// =================================================================================
extern "C" void kernel_launch(void* const* d_in, const int* in_sizes, int n_in,
                              void* d_out, int out_size) {
    const float* hidden = (const float*)d_in[0];
    const float* s2     = (const float*)d_in[1];
    const float* W_r1   = (const float*)d_in[2];
    const float* b_r1   = (const float*)d_in[3];
    const float* W_r2   = (const float*)d_in[4];
    const float* b_r2   = (const float*)d_in[5];
    const float* W_s1   = (const float*)d_in[6];
    const float* b_s1   = (const float*)d_in[7];
    float* out = (float*)d_out;

    static bool attr_done = false;
    if (!attr_done) {
        cudaFuncSetAttribute(s1_mma_kernel,
                             cudaFuncAttributeMaxDynamicSharedMemorySize, S1_SMEM);
        attr_done = true;
    }

    conv_hidden_kernel<<<(LL * TT * (DD / 4)) / 256, 256>>>(hidden);
    conv_wt_kernel<<<dim3(DD / 32, DD / 32, LL), dim3(32, 8)>>>(W_s1);

    dim3 g1(1, TT / 128, LL);
    router_gemm_kernel<<<g1, 256>>>(hidden, W_r1, b_r1);
    logits_kernel<<<(LL * TT) / 8, 256>>>(W_r2, b_r2);
    topk_kernel<<<LL, 1024>>>();

    copy_s2_kernel<<<dim3(KK, LL), 256>>>(s2, out);
    dim3 g2(DD / 128, KK / 128, LL);
    s1_mma_kernel<<<g2, 256, S1_SMEM>>>(b_s1, out);
}

// round 7
// speedup vs baseline: 2.7065x; 1.5384x over previous
#include <cuda_runtime.h>
#include <cuda_bf16.h>
#include <cstdint>

// Problem dims
#define LL 16
#define TT 2048
#define DD 2048
#define RR 128
#define KK 1024   // tokens routed to s2 (top-k); TT-KK tokens need the s1 GEMM

// ---------------- scratch (device globals: no allocation allowed) ----------------
__device__ float g_hrelu[(size_t)LL * TT * RR];
__device__ float g_logits[LL * TT];
__device__ int   g_copy_idx[LL * KK];
__device__ int   g_comp_idx[LL * KK];
// bf16 hi/lo split operands for the s1 GEMM (W transposed to [N,K])
__device__ __align__(1024) __nv_bfloat16 g_hid_hi[(size_t)LL * TT * DD];
__device__ __align__(1024) __nv_bfloat16 g_hid_lo[(size_t)LL * TT * DD];
__device__ __align__(1024) __nv_bfloat16 g_wt_hi[(size_t)LL * DD * DD];
__device__ __align__(1024) __nv_bfloat16 g_wt_lo[(size_t)LL * DD * DD];

// ---------------- helpers ----------------
__device__ __forceinline__ uint32_t smem_u32(const void* p) {
    uint32_t a;
    asm("{ .reg .u64 t; cvta.to.shared.u64 t, %1; cvt.u32.u64 %0, t; }" : "=r"(a) : "l"(p));
    return a;
}
__device__ __forceinline__ unsigned long long pack2(float lo, float hi) {
    unsigned long long r;
    asm("mov.b64 %0, {%1, %2};" : "=l"(r) : "f"(lo), "f"(hi));
    return r;
}
__device__ __forceinline__ void unpack2(unsigned long long v, float& lo, float& hi) {
    asm("mov.b64 {%0, %1}, %2;" : "=f"(lo), "=f"(hi) : "l"(v));
}
__device__ __forceinline__ unsigned long long fma2(unsigned long long a,
                                                   unsigned long long b,
                                                   unsigned long long c) {
    unsigned long long d;
    asm("fma.rn.f32x2 %0, %1, %2, %3;" : "=l"(d) : "l"(a), "l"(b), "l"(c));
    return d;
}
__device__ __forceinline__ void cp16(uint32_t s, const void* g) {
    asm volatile("cp.async.cg.shared.global [%0], [%1], 16;" :: "r"(s), "l"(g));
}
#define CP_COMMIT() asm volatile("cp.async.commit_group;" ::: "memory")
#define CP_WAIT(n)  asm volatile("cp.async.wait_group %0;" :: "n"(n) : "memory")

__device__ __forceinline__ void ldsm4(uint32_t* r, uint32_t addr) {
    asm volatile("ldmatrix.sync.aligned.m8n8.x4.shared.b16 {%0,%1,%2,%3}, [%4];"
                 : "=r"(r[0]), "=r"(r[1]), "=r"(r[2]), "=r"(r[3]) : "r"(addr));
}
__device__ __forceinline__ void mma_bf16(float* c, const uint32_t* a,
                                         uint32_t b0, uint32_t b1) {
    asm volatile(
        "mma.sync.aligned.m16n8k16.row.col.f32.bf16.bf16.f32 "
        "{%0,%1,%2,%3}, {%4,%5,%6,%7}, {%8,%9}, {%0,%1,%2,%3};"
        : "+f"(c[0]), "+f"(c[1]), "+f"(c[2]), "+f"(c[3])
        : "r"(a[0]), "r"(a[1]), "r"(a[2]), "r"(a[3]), "r"(b0), "r"(b1));
}

// =================================================================================
// Conversion kernels
// =================================================================================
__global__ __launch_bounds__(256) void conv_hidden_kernel(const float* __restrict__ hidden) {
    size_t i = ((size_t)blockIdx.x * 256 + threadIdx.x) * 4;
    float4 v = *(const float4*)(hidden + i);
    __nv_bfloat16 h0 = __float2bfloat16_rn(v.x), h1 = __float2bfloat16_rn(v.y);
    __nv_bfloat16 h2 = __float2bfloat16_rn(v.z), h3 = __float2bfloat16_rn(v.w);
    __nv_bfloat16 l0 = __float2bfloat16_rn(v.x - __bfloat162float(h0));
    __nv_bfloat16 l1 = __float2bfloat16_rn(v.y - __bfloat162float(h1));
    __nv_bfloat16 l2 = __float2bfloat16_rn(v.z - __bfloat162float(h2));
    __nv_bfloat16 l3 = __float2bfloat16_rn(v.w - __bfloat162float(h3));
    __nv_bfloat162 hp0(h0, h1), hp1(h2, h3), lp0(l0, l1), lp1(l2, l3);
    uint2 hw, lw;
    hw.x = *(uint32_t*)&hp0; hw.y = *(uint32_t*)&hp1;
    lw.x = *(uint32_t*)&lp0; lw.y = *(uint32_t*)&lp1;
    *(uint2*)(g_hid_hi + i) = hw;
    *(uint2*)(g_hid_lo + i) = lw;
}

// W_s1 [l, k, n] fp32 -> transposed bf16 hi/lo [l, n, k]
__global__ __launch_bounds__(256) void conv_wt_kernel(const float* __restrict__ Ws1) {
    __shared__ float tile[32][33];
    const int l  = blockIdx.z;
    const int kb = blockIdx.y * 32;
    const int nb = blockIdx.x * 32;
    const int x  = threadIdx.x;
    const int ty = threadIdx.y;
    const float* src = Ws1 + (size_t)l * DD * DD;
#pragma unroll
    for (int j = ty; j < 32; j += 8)
        tile[j][x] = src[(size_t)(kb + j) * DD + nb + x];
    __syncthreads();
#pragma unroll
    for (int j = ty; j < 32; j += 8) {
        float v = tile[x][j];   // = W[kb+x, nb+j]
        __nv_bfloat16 hi = __float2bfloat16_rn(v);
        __nv_bfloat16 lo = __float2bfloat16_rn(v - __bfloat162float(hi));
        size_t o = (size_t)l * DD * DD + (size_t)(nb + j) * DD + kb + x;
        g_wt_hi[o] = hi;
        g_wt_lo[o] = lo;
    }
}

// =================================================================================
// Router hidden GEMM (fp32 f32x2 — topk ordering must match reference)
// =================================================================================
__global__ __launch_bounds__(256, 2)
void router_gemm_kernel(const float* __restrict__ hidden,
                        const float* __restrict__ W1,
                        const float* __restrict__ b1) {
    const int l  = blockIdx.z;
    const int mt = blockIdx.y;

    const float* A  = hidden + (size_t)l * TT * DD + (size_t)mt * 128 * DD;
    const float* Bp = W1 + (size_t)l * DD * RR;

    __shared__ float as[16][132];
    __shared__ float bs[16][128];

    const int tid   = threadIdx.x;
    const int a_row = tid >> 2;
    const int a_kq  = tid & 3;
    const int b_k   = tid >> 5;
    const int b_c   = (tid & 31) << 2;
    const int tx    = tid & 15;
    const int ty    = tid >> 4;
    const int m0    = ty * 8;
    const int n0    = tx * 8;

    unsigned long long acc[8][4];
#pragma unroll
    for (int i = 0; i < 8; i++)
#pragma unroll
        for (int j = 0; j < 4; j++) acc[i][j] = 0ULL;

    float4 pa0 = *(const float4*)(A + (size_t)a_row * DD + a_kq * 4);
    float4 pa1 = *(const float4*)(A + (size_t)(a_row + 64) * DD + a_kq * 4);
    float4 pb0 = *(const float4*)(Bp + (size_t)b_k * RR + b_c);
    float4 pb1 = *(const float4*)(Bp + (size_t)(b_k + 8) * RR + b_c);

    for (int kt = 0; kt < DD / 16; kt++) {
        __syncthreads();
        as[a_kq * 4 + 0][a_row]      = pa0.x;
        as[a_kq * 4 + 1][a_row]      = pa0.y;
        as[a_kq * 4 + 2][a_row]      = pa0.z;
        as[a_kq * 4 + 3][a_row]      = pa0.w;
        as[a_kq * 4 + 0][a_row + 64] = pa1.x;
        as[a_kq * 4 + 1][a_row + 64] = pa1.y;
        as[a_kq * 4 + 2][a_row + 64] = pa1.z;
        as[a_kq * 4 + 3][a_row + 64] = pa1.w;
        *(float4*)&bs[b_k][b_c]     = pb0;
        *(float4*)&bs[b_k + 8][b_c] = pb1;
        __syncthreads();
        if (kt + 1 < DD / 16) {
            const int kb = (kt + 1) * 16;
            pa0 = *(const float4*)(A + (size_t)a_row * DD + kb + a_kq * 4);
            pa1 = *(const float4*)(A + (size_t)(a_row + 64) * DD + kb + a_kq * 4);
            pb0 = *(const float4*)(Bp + (size_t)(kb + b_k) * RR + b_c);
            pb1 = *(const float4*)(Bp + (size_t)(kb + b_k + 8) * RR + b_c);
        }
#pragma unroll
        for (int k = 0; k < 16; k++) {
            float4 am0 = *(const float4*)&as[k][m0];
            float4 am1 = *(const float4*)&as[k][m0 + 4];
            float4 bn0 = *(const float4*)&bs[k][n0];
            float4 bn1 = *(const float4*)&bs[k][n0 + 4];
            unsigned long long bp[4] = { pack2(bn0.x, bn0.y), pack2(bn0.z, bn0.w),
                                         pack2(bn1.x, bn1.y), pack2(bn1.z, bn1.w) };
            float am[8] = { am0.x, am0.y, am0.z, am0.w, am1.x, am1.y, am1.z, am1.w };
#pragma unroll
            for (int i = 0; i < 8; i++) {
                unsigned long long ai = pack2(am[i], am[i]);
#pragma unroll
                for (int j = 0; j < 4; j++) acc[i][j] = fma2(ai, bp[j], acc[i][j]);
            }
        }
    }

    float bias[8];
#pragma unroll
    for (int j = 0; j < 8; j++) bias[j] = b1[l * RR + n0 + j];
#pragma unroll
    for (int i = 0; i < 8; i++) {
        float v[8];
#pragma unroll
        for (int j = 0; j < 4; j++) unpack2(acc[i][j], v[2 * j], v[2 * j + 1]);
        float4 o0, o1;
        o0.x = fmaxf(v[0] + bias[0], 0.f); o0.y = fmaxf(v[1] + bias[1], 0.f);
        o0.z = fmaxf(v[2] + bias[2], 0.f); o0.w = fmaxf(v[3] + bias[3], 0.f);
        o1.x = fmaxf(v[4] + bias[4], 0.f); o1.y = fmaxf(v[5] + bias[5], 0.f);
        o1.z = fmaxf(v[6] + bias[6], 0.f); o1.w = fmaxf(v[7] + bias[7], 0.f);
        float* dst = g_hrelu + ((size_t)l * TT + mt * 128 + m0 + i) * RR + n0;
        *(float4*)dst       = o0;
        *(float4*)(dst + 4) = o1;
    }
}

// =================================================================================
// logits / topk / copy
// =================================================================================
__global__ void logits_kernel(const float* __restrict__ W2, const float* __restrict__ b2) {
    const int gw   = (blockIdx.x * blockDim.x + threadIdx.x) >> 5;
    const int lane = threadIdx.x & 31;
    const int l = gw >> 11;
    const int t = gw & 2047;
    const float* h = g_hrelu + ((size_t)l * TT + t) * RR;
    const float* w = W2 + l * RR;
    float s = 0.f;
#pragma unroll
    for (int r = 0; r < RR; r += 32) s += h[r + lane] * w[r + lane];
#pragma unroll
    for (int o = 16; o; o >>= 1) s += __shfl_xor_sync(0xffffffffu, s, o);
    if (lane == 0) g_logits[l * TT + t] = s + b2[l];
}

__global__ void topk_kernel() {
    __shared__ unsigned long long keys[2048];
    const int l = blockIdx.x;
    const int tid = threadIdx.x;
    for (int i = tid; i < 2048; i += 1024) {
        float f = g_logits[l * TT + i];
        unsigned u = __float_as_uint(f);
        u = (u & 0x80000000u) ? ~u : (u | 0x80000000u);
        keys[i] = ((unsigned long long)(~u) << 32) | (unsigned)i;
    }
    __syncthreads();
    for (int ks = 2; ks <= 2048; ks <<= 1) {
        for (int j = ks >> 1; j > 0; j >>= 1) {
            for (int i = tid; i < 2048; i += 1024) {
                int ixj = i ^ j;
                if (ixj > i) {
                    unsigned long long a = keys[i], b = keys[ixj];
                    bool asc = ((i & ks) == 0);
                    if ((a > b) == asc) { keys[i] = b; keys[ixj] = a; }
                }
            }
            __syncthreads();
        }
    }
    for (int i = tid; i < 2048; i += 1024) {
        int idx = (int)(keys[i] & 0xFFFFFFFFu);
        if (i < KK) g_copy_idx[l * KK + i]        = idx;
        else        g_comp_idx[l * KK + (i - KK)] = idx;
    }
}

__global__ void copy_s2_kernel(const float* __restrict__ s2, float* __restrict__ out) {
    const int l = blockIdx.y;
    const int t = g_copy_idx[l * KK + blockIdx.x];
    const float4* src = (const float4*)(s2  + ((size_t)l * TT + t) * DD);
    float4*       dst = (float4*)      (out + ((size_t)l * TT + t) * DD);
#pragma unroll
    for (int i = threadIdx.x; i < DD / 4; i += 256) dst[i] = src[i];
}

// =================================================================================
// s1 GEMM via mma.sync bf16 hi/lo 3-pass.
// CTA tile 128(M gathered rows) x 128(N), BK=32, 8 warps (2M x 4N), warp 64x32.
// 3-stage cp.async ring, ONE __syncthreads per K-iter:
//   [CP_WAIT(slot it) ; sync ; issue loads slot it+2 ; compute slot it]
// The single sync both publishes every thread's cp.async for slot it and
// proves all warps finished computing it-1, so overwriting (it+2)%3 == (it-1)%3
// is safe. grid (DD/128=16, KK/128=8, LL=16), 256 threads.
// =================================================================================
#define ROWB   80
#define MATB   (128 * ROWB)      // 10240 B per matrix
#define STAGEB (4 * MATB)        // A_hi, A_lo, B_hi, B_lo
#define S1_SMEM (1024 + 3 * STAGEB)   // 123904 B

__global__ __launch_bounds__(256, 1)
void s1_mma_kernel(const float* __restrict__ bs1, float* __restrict__ out) {
    extern __shared__ __align__(128) char smem[];
    const uint32_t sb = smem_u32(smem);
    int* rows_s = (int*)smem;
    const int tid  = threadIdx.x;
    const int lane = tid & 31;
    const int wid  = tid >> 5;
    const int nt = blockIdx.x, mt = blockIdx.y, l = blockIdx.z;

    if (tid < 128) rows_s[tid] = g_comp_idx[l * KK + mt * 128 + tid];
    __syncthreads();

    // ---- cp.async source pointers: 2 chunks/thread/matrix ----
    const __nv_bfloat16 *pa_hi[2], *pa_lo[2], *pb_hi[2], *pb_lo[2];
    uint32_t sdst[2];
#pragma unroll
    for (int q = 0; q < 2; q++) {
        const int c   = tid + q * 256;       // 0..511
        const int row = c >> 2, ch = c & 3;  // row 0..127, 16B chunk 0..3
        const size_t aoff = ((size_t)l * TT + rows_s[row]) * DD + ch * 8;
        pa_hi[q] = g_hid_hi + aoff;
        pa_lo[q] = g_hid_lo + aoff;
        const size_t boff = ((size_t)l * DD + nt * 128 + row) * DD + ch * 8;
        pb_hi[q] = g_wt_hi + boff;
        pb_lo[q] = g_wt_lo + boff;
        sdst[q] = (uint32_t)(row * ROWB + ch * 16);
    }

    auto load_stage = [&](int buf, int it) {
        const uint32_t base = sb + 1024 + buf * STAGEB;
        const int ko = it * 32;
#pragma unroll
        for (int q = 0; q < 2; q++) {
            cp16(base + 0 * MATB + sdst[q], pa_hi[q] + ko);
            cp16(base + 1 * MATB + sdst[q], pa_lo[q] + ko);
            cp16(base + 2 * MATB + sdst[q], pb_hi[q] + ko);
            cp16(base + 3 * MATB + sdst[q], pb_lo[q] + ko);
        }
        CP_COMMIT();
    };

    // ---- ldmatrix per-lane offsets ----
    const int warp_m = wid & 1;   // 0..1
    const int warp_n = wid >> 1;  // 0..3
    const uint32_t offA = (uint32_t)((warp_m * 64 + (lane & 15)) * ROWB +
                                     ((lane & 16) ? 16 : 0));
    const uint32_t offB = (uint32_t)((warp_n * 32 + (lane & 7) + ((lane & 16) ? 8 : 0)) * ROWB +
                                     ((lane & 8) ? 16 : 0));

    float acc[4][4][4];
#pragma unroll
    for (int i = 0; i < 4; i++)
#pragma unroll
        for (int j = 0; j < 4; j++)
#pragma unroll
            for (int k = 0; k < 4; k++) acc[i][j][k] = 0.f;

    load_stage(0, 0);
    load_stage(1, 1);

    const int NIT = DD / 32;   // 64
    int slot = 0;              // slot of iteration `it` in the 3-ring
    for (int it = 0; it < NIT; it++) {
        if (it + 1 < NIT) { CP_WAIT(1); }   // slot `it` complete (this thread)
        else              { CP_WAIT(0); }
        __syncthreads();                    // publish slot `it`; all done it-1
        if (it + 2 < NIT) {
            int ns = slot + 2; if (ns >= 3) ns -= 3;
            load_stage(ns, it + 2);         // overwrites slot (it-1)%3 — safe
        }

        const uint32_t base = sb + 1024 + slot * STAGEB;
        const uint32_t Ah = base + 0 * MATB, Al = base + 1 * MATB;
        const uint32_t Bh = base + 2 * MATB, Bl = base + 3 * MATB;
#pragma unroll
        for (int kk = 0; kk < 2; kk++) {
            const uint32_t kof = kk * 32;
            uint32_t ah[4][4], al[4][4], bh[2][4], bl[2][4];
#pragma unroll
            for (int mf = 0; mf < 4; mf++) {
                const uint32_t o = offA + mf * 16 * ROWB + kof;
                ldsm4(ah[mf], Ah + o);
                ldsm4(al[mf], Al + o);
            }
#pragma unroll
            for (int nf2 = 0; nf2 < 2; nf2++) {
                const uint32_t o = offB + nf2 * 16 * ROWB + kof;
                ldsm4(bh[nf2], Bh + o);
                ldsm4(bl[nf2], Bl + o);
            }
#pragma unroll
            for (int mf = 0; mf < 4; mf++) {
#pragma unroll
                for (int nf = 0; nf < 4; nf++) {
                    const int n2 = nf >> 1, s = (nf & 1) * 2;
                    mma_bf16(acc[mf][nf], ah[mf], bh[n2][s], bh[n2][s + 1]);
                    mma_bf16(acc[mf][nf], ah[mf], bl[n2][s], bl[n2][s + 1]);
                    mma_bf16(acc[mf][nf], al[mf], bh[n2][s], bh[n2][s + 1]);
                }
            }
        }
        if (++slot == 3) slot = 0;
    }

    // ---- epilogue: +bias, scatter rows ----
    const int g   = lane >> 2;
    const int tig = lane & 3;
#pragma unroll
    for (int mf = 0; mf < 4; mf++) {
        const int m0 = warp_m * 64 + mf * 16 + g;
        const int r0 = rows_s[m0];
        const int r1 = rows_s[m0 + 8];
        float* d0 = out + ((size_t)l * TT + r0) * DD;
        float* d1 = out + ((size_t)l * TT + r1) * DD;
#pragma unroll
        for (int nf = 0; nf < 4; nf++) {
            const int n = nt * 128 + warp_n * 32 + nf * 8 + tig * 2;
            const float2 bv = *(const float2*)(bs1 + l * DD + n);
            float2 o0, o1;
            o0.x = acc[mf][nf][0] + bv.x; o0.y = acc[mf][nf][1] + bv.y;
            o1.x = acc[mf][nf][2] + bv.x; o1.y = acc[mf][nf][3] + bv.y;
            *(float2*)(d0 + n) = o0;
            *(float2*)(d1 + n) = o1;
        }
    }
}

// =================================================================================
extern "C" void kernel_launch(void* const* d_in, const int* in_sizes, int n_in,
                              void* d_out, int out_size) {
    const float* hidden = (const float*)d_in[0];
    const float* s2     = (const float*)d_in[1];
    const float* W_r1   = (const float*)d_in[2];
    const float* b_r1   = (const float*)d_in[3];
    const float* W_r2   = (const float*)d_in[4];
    const float* b_r2   = (const float*)d_in[5];
    const float* W_s1   = (const float*)d_in[6];
    const float* b_s1   = (const float*)d_in[7];
    float* out = (float*)d_out;

    static bool attr_done = false;
    if (!attr_done) {
        cudaFuncSetAttribute(s1_mma_kernel,
                             cudaFuncAttributeMaxDynamicSharedMemorySize, S1_SMEM);
        attr_done = true;
    }

    conv_hidden_kernel<<<(LL * TT * (DD / 4)) / 256, 256>>>(hidden);
    conv_wt_kernel<<<dim3(DD / 32, DD / 32, LL), dim3(32, 8)>>>(W_s1);

    dim3 g1(1, TT / 128, LL);
    router_gemm_kernel<<<g1, 256>>>(hidden, W_r1, b_r1);
    logits_kernel<<<(LL * TT) / 8, 256>>>(W_r2, b_r2);
    topk_kernel<<<LL, 1024>>>();

    copy_s2_kernel<<<dim3(KK, LL), 256>>>(s2, out);
    dim3 g2(DD / 128, KK / 128, LL);
    s1_mma_kernel<<<g2, 256, S1_SMEM>>>(b_s1, out);
}

// round 11
// speedup vs baseline: 3.0511x; 1.1273x over previous
#include <cuda_runtime.h>
#include <cuda_fp16.h>
#include <cstdint>

// Problem dims
#define LL 16
#define TT 2048
#define DD 2048
#define RR 128
#define KK 1024   // tokens routed to s2 (top-k); TT-KK tokens need the s1 GEMM

// ---------------- scratch (device globals: no allocation allowed) ----------------
__device__ float g_hrelu[(size_t)LL * TT * RR];
__device__ float g_logits[LL * TT];
__device__ int   g_copy_idx[LL * KK];
__device__ int   g_comp_idx[LL * KK];
// fp16 hi/lo split operands (22-bit effective mantissa via 2-term split)
__device__ __align__(1024) __half g_hid_hi[(size_t)LL * TT * DD];
__device__ __align__(1024) __half g_hid_lo[(size_t)LL * TT * DD];
__device__ __align__(1024) __half g_wt_hi[(size_t)LL * DD * DD];   // W_s1^T [l,n,k]
__device__ __align__(1024) __half g_wt_lo[(size_t)LL * DD * DD];
__device__ __align__(1024) __half g_wr1_hi[(size_t)LL * RR * DD];  // W_r1^T [l,r,k]
__device__ __align__(1024) __half g_wr1_lo[(size_t)LL * RR * DD];

// ---------------- helpers ----------------
__device__ __forceinline__ uint32_t smem_u32(const void* p) {
    uint32_t a;
    asm("{ .reg .u64 t; cvta.to.shared.u64 t, %1; cvt.u32.u64 %0, t; }" : "=r"(a) : "l"(p));
    return a;
}
__device__ __forceinline__ void cp16(uint32_t s, const void* g) {
    asm volatile("cp.async.cg.shared.global [%0], [%1], 16;" :: "r"(s), "l"(g));
}
#define CP_COMMIT() asm volatile("cp.async.commit_group;" ::: "memory")
#define CP_WAIT(n)  asm volatile("cp.async.wait_group %0;" :: "n"(n) : "memory")

__device__ __forceinline__ void ldsm4(uint32_t* r, uint32_t addr) {
    asm volatile("ldmatrix.sync.aligned.m8n8.x4.shared.b16 {%0,%1,%2,%3}, [%4];"
                 : "=r"(r[0]), "=r"(r[1]), "=r"(r[2]), "=r"(r[3]) : "r"(addr));
}
__device__ __forceinline__ void mma_fp16(float* c, const uint32_t* a,
                                         uint32_t b0, uint32_t b1) {
    asm volatile(
        "mma.sync.aligned.m16n8k16.row.col.f32.f16.f16.f32 "
        "{%0,%1,%2,%3}, {%4,%5,%6,%7}, {%8,%9}, {%0,%1,%2,%3};"
        : "+f"(c[0]), "+f"(c[1]), "+f"(c[2]), "+f"(c[3])
        : "r"(a[0]), "r"(a[1]), "r"(a[2]), "r"(a[3]), "r"(b0), "r"(b1));
}

// =================================================================================
// Conversion kernels (fp32 -> fp16 hi + fp16 lo; a = ah + al + O(2^-22 |a|))
// =================================================================================
__global__ __launch_bounds__(256) void conv_hidden_kernel(const float* __restrict__ hidden) {
    size_t i = ((size_t)blockIdx.x * 256 + threadIdx.x) * 4;
    float4 v = *(const float4*)(hidden + i);
    __half h0 = __float2half_rn(v.x), h1 = __float2half_rn(v.y);
    __half h2 = __float2half_rn(v.z), h3 = __float2half_rn(v.w);
    __half l0 = __float2half_rn(v.x - __half2float(h0));
    __half l1 = __float2half_rn(v.y - __half2float(h1));
    __half l2 = __float2half_rn(v.z - __half2float(h2));
    __half l3 = __float2half_rn(v.w - __half2float(h3));
    __half2 hp0 = __halves2half2(h0, h1), hp1 = __halves2half2(h2, h3);
    __half2 lp0 = __halves2half2(l0, l1), lp1 = __halves2half2(l2, l3);
    uint2 hw, lw;
    hw.x = *(uint32_t*)&hp0; hw.y = *(uint32_t*)&hp1;
    lw.x = *(uint32_t*)&lp0; lw.y = *(uint32_t*)&lp1;
    *(uint2*)(g_hid_hi + i) = hw;
    *(uint2*)(g_hid_lo + i) = lw;
}

// W_s1 [l, k, n] fp32 -> transposed fp16 hi/lo [l, n, k]
__global__ __launch_bounds__(256) void conv_wt_kernel(const float* __restrict__ Ws1) {
    __shared__ float tile[32][33];
    const int l  = blockIdx.z;
    const int kb = blockIdx.y * 32;
    const int nb = blockIdx.x * 32;
    const int x  = threadIdx.x;
    const int ty = threadIdx.y;
    const float* src = Ws1 + (size_t)l * DD * DD;
#pragma unroll
    for (int j = ty; j < 32; j += 8)
        tile[j][x] = src[(size_t)(kb + j) * DD + nb + x];
    __syncthreads();
#pragma unroll
    for (int j = ty; j < 32; j += 8) {
        float v = tile[x][j];   // = W[kb+x, nb+j]
        __half hi = __float2half_rn(v);
        __half lo = __float2half_rn(v - __half2float(hi));
        size_t o = (size_t)l * DD * DD + (size_t)(nb + j) * DD + kb + x;
        g_wt_hi[o] = hi;
        g_wt_lo[o] = lo;
    }
}

// W_r1 [l, d, r] fp32 -> transposed fp16 hi/lo [l, r, d]
__global__ __launch_bounds__(256) void conv_wr1_kernel(const float* __restrict__ Wr1) {
    __shared__ float tile[32][33];
    const int l  = blockIdx.z;
    const int db = blockIdx.y * 32;
    const int rb = blockIdx.x * 32;
    const int x  = threadIdx.x;
    const int ty = threadIdx.y;
    const float* src = Wr1 + (size_t)l * DD * RR;
#pragma unroll
    for (int j = ty; j < 32; j += 8)
        tile[j][x] = src[(size_t)(db + j) * RR + rb + x];
    __syncthreads();
#pragma unroll
    for (int j = ty; j < 32; j += 8) {
        float v = tile[x][j];   // = W[d=db+x, r=rb+j]
        __half hi = __float2half_rn(v);
        __half lo = __float2half_rn(v - __half2float(hi));
        size_t o = (size_t)l * RR * DD + (size_t)(rb + j) * DD + db + x;
        g_wr1_hi[o] = hi;
        g_wr1_lo[o] = lo;
    }
}

// =================================================================================
// Shared HMMA tile machinery: CTA tile 128(M) x 128(N), BK=32, 8 warps (2M x 4N),
// 3-stage cp.async ring with ONE __syncthreads per K-iter (validated R7 pattern).
// =================================================================================
#define ROWB   80
#define MATB   (128 * ROWB)      // 10240 B per matrix
#define STAGEB (4 * MATB)        // A_hi, A_lo, B_hi, B_lo
#define S1_SMEM (1024 + 3 * STAGEB)   // 123904 B

// ---------------------------------------------------------------------------------
// Router hidden GEMM on HMMA: g_hrelu[l,t,r] = relu(hidden@W_r1 + b_r1)
// fp16 hi/lo 3-pass. grid (TT/128=16, LL=16), 256 threads.
// ---------------------------------------------------------------------------------
__global__ __launch_bounds__(256, 1)
void router_mma_kernel(const float* __restrict__ b1) {
    extern __shared__ __align__(128) char smem[];
    const uint32_t sb = smem_u32(smem);
    const int tid  = threadIdx.x;
    const int lane = tid & 31;
    const int wid  = tid >> 5;
    const int mt = blockIdx.x, l = blockIdx.y;

    const __half *pa_hi[2], *pa_lo[2], *pb_hi[2], *pb_lo[2];
    uint32_t sdst[2];
#pragma unroll
    for (int q = 0; q < 2; q++) {
        const int c   = tid + q * 256;
        const int row = c >> 2, ch = c & 3;
        const size_t aoff = ((size_t)l * TT + mt * 128 + row) * DD + ch * 8;
        pa_hi[q] = g_hid_hi + aoff;
        pa_lo[q] = g_hid_lo + aoff;
        const size_t boff = ((size_t)l * RR + row) * DD + ch * 8;
        pb_hi[q] = g_wr1_hi + boff;
        pb_lo[q] = g_wr1_lo + boff;
        sdst[q] = (uint32_t)(row * ROWB + ch * 16);
    }

    auto load_stage = [&](int buf, int it) {
        const uint32_t base = sb + 1024 + buf * STAGEB;
        const int ko = it * 32;
#pragma unroll
        for (int q = 0; q < 2; q++) {
            cp16(base + 0 * MATB + sdst[q], pa_hi[q] + ko);
            cp16(base + 1 * MATB + sdst[q], pa_lo[q] + ko);
            cp16(base + 2 * MATB + sdst[q], pb_hi[q] + ko);
            cp16(base + 3 * MATB + sdst[q], pb_lo[q] + ko);
        }
        CP_COMMIT();
    };

    const int warp_m = wid & 1;
    const int warp_n = wid >> 1;
    const uint32_t offA = (uint32_t)((warp_m * 64 + (lane & 15)) * ROWB +
                                     ((lane & 16) ? 16 : 0));
    const uint32_t offB = (uint32_t)((warp_n * 32 + (lane & 7) + ((lane & 16) ? 8 : 0)) * ROWB +
                                     ((lane & 8) ? 16 : 0));

    float acc[4][4][4];
#pragma unroll
    for (int i = 0; i < 4; i++)
#pragma unroll
        for (int j = 0; j < 4; j++)
#pragma unroll
            for (int k = 0; k < 4; k++) acc[i][j][k] = 0.f;

    load_stage(0, 0);
    load_stage(1, 1);

    const int NIT = DD / 32;
    int slot = 0;
    for (int it = 0; it < NIT; it++) {
        if (it + 1 < NIT) { CP_WAIT(1); } else { CP_WAIT(0); }
        __syncthreads();
        if (it + 2 < NIT) {
            int ns = slot + 2; if (ns >= 3) ns -= 3;
            load_stage(ns, it + 2);
        }
        const uint32_t base = sb + 1024 + slot * STAGEB;
        const uint32_t Ah = base + 0 * MATB, Al = base + 1 * MATB;
        const uint32_t Bh = base + 2 * MATB, Bl = base + 3 * MATB;
#pragma unroll
        for (int kk = 0; kk < 2; kk++) {
            const uint32_t kof = kk * 32;
            uint32_t ah[4][4], al[4][4], bh[2][4], bl[2][4];
#pragma unroll
            for (int mf = 0; mf < 4; mf++) {
                const uint32_t o = offA + mf * 16 * ROWB + kof;
                ldsm4(ah[mf], Ah + o);
                ldsm4(al[mf], Al + o);
            }
#pragma unroll
            for (int nf2 = 0; nf2 < 2; nf2++) {
                const uint32_t o = offB + nf2 * 16 * ROWB + kof;
                ldsm4(bh[nf2], Bh + o);
                ldsm4(bl[nf2], Bl + o);
            }
#pragma unroll
            for (int mf = 0; mf < 4; mf++) {
#pragma unroll
                for (int nf = 0; nf < 4; nf++) {
                    const int n2 = nf >> 1, s = (nf & 1) * 2;
                    mma_fp16(acc[mf][nf], ah[mf], bh[n2][s], bh[n2][s + 1]);
                    mma_fp16(acc[mf][nf], ah[mf], bl[n2][s], bl[n2][s + 1]);
                    mma_fp16(acc[mf][nf], al[mf], bh[n2][s], bh[n2][s + 1]);
                }
            }
        }
        if (++slot == 3) slot = 0;
    }

    // epilogue: +bias, relu, store fp32 to g_hrelu
    const int g   = lane >> 2;
    const int tig = lane & 3;
#pragma unroll
    for (int mf = 0; mf < 4; mf++) {
        const int m0 = warp_m * 64 + mf * 16 + g;
        float* d0 = g_hrelu + ((size_t)l * TT + mt * 128 + m0) * RR;
        float* d1 = g_hrelu + ((size_t)l * TT + mt * 128 + m0 + 8) * RR;
#pragma unroll
        for (int nf = 0; nf < 4; nf++) {
            const int n = warp_n * 32 + nf * 8 + tig * 2;
            const float2 bv = *(const float2*)(b1 + l * RR + n);
            float2 o0, o1;
            o0.x = fmaxf(acc[mf][nf][0] + bv.x, 0.f);
            o0.y = fmaxf(acc[mf][nf][1] + bv.y, 0.f);
            o1.x = fmaxf(acc[mf][nf][2] + bv.x, 0.f);
            o1.y = fmaxf(acc[mf][nf][3] + bv.y, 0.f);
            *(float2*)(d0 + n) = o0;
            *(float2*)(d1 + n) = o1;
        }
    }
}

// =================================================================================
// logits / topk / copy (unchanged, validated)
// =================================================================================
__global__ void logits_kernel(const float* __restrict__ W2, const float* __restrict__ b2) {
    const int gw   = (blockIdx.x * blockDim.x + threadIdx.x) >> 5;
    const int lane = threadIdx.x & 31;
    const int l = gw >> 11;
    const int t = gw & 2047;
    const float* h = g_hrelu + ((size_t)l * TT + t) * RR;
    const float* w = W2 + l * RR;
    float s = 0.f;
#pragma unroll
    for (int r = 0; r < RR; r += 32) s += h[r + lane] * w[r + lane];
#pragma unroll
    for (int o = 16; o; o >>= 1) s += __shfl_xor_sync(0xffffffffu, s, o);
    if (lane == 0) g_logits[l * TT + t] = s + b2[l];
}

__global__ void topk_kernel() {
    __shared__ unsigned long long keys[2048];
    const int l = blockIdx.x;
    const int tid = threadIdx.x;
    for (int i = tid; i < 2048; i += 1024) {
        float f = g_logits[l * TT + i];
        unsigned u = __float_as_uint(f);
        u = (u & 0x80000000u) ? ~u : (u | 0x80000000u);
        keys[i] = ((unsigned long long)(~u) << 32) | (unsigned)i;
    }
    __syncthreads();
    for (int ks = 2; ks <= 2048; ks <<= 1) {
        for (int j = ks >> 1; j > 0; j >>= 1) {
            for (int i = tid; i < 2048; i += 1024) {
                int ixj = i ^ j;
                if (ixj > i) {
                    unsigned long long a = keys[i], b = keys[ixj];
                    bool asc = ((i & ks) == 0);
                    if ((a > b) == asc) { keys[i] = b; keys[ixj] = a; }
                }
            }
            __syncthreads();
        }
    }
    for (int i = tid; i < 2048; i += 1024) {
        int idx = (int)(keys[i] & 0xFFFFFFFFu);
        if (i < KK) g_copy_idx[l * KK + i]        = idx;
        else        g_comp_idx[l * KK + (i - KK)] = idx;
    }
}

__global__ void copy_s2_kernel(const float* __restrict__ s2, float* __restrict__ out) {
    const int l = blockIdx.y;
    const int t = g_copy_idx[l * KK + blockIdx.x];
    const float4* src = (const float4*)(s2  + ((size_t)l * TT + t) * DD);
    float4*       dst = (float4*)      (out + ((size_t)l * TT + t) * DD);
#pragma unroll
    for (int i = threadIdx.x; i < DD / 4; i += 256) dst[i] = src[i];
}

// =================================================================================
// s1 GEMM (fp16 hi/lo 3-pass, validated R7 structure)
// grid (DD/128=16, KK/128=8, LL=16), 256 threads.
// =================================================================================
__global__ __launch_bounds__(256, 1)
void s1_mma_kernel(const float* __restrict__ bs1, float* __restrict__ out) {
    extern __shared__ __align__(128) char smem[];
    const uint32_t sb = smem_u32(smem);
    int* rows_s = (int*)smem;
    const int tid  = threadIdx.x;
    const int lane = tid & 31;
    const int wid  = tid >> 5;
    const int nt = blockIdx.x, mt = blockIdx.y, l = blockIdx.z;

    if (tid < 128) rows_s[tid] = g_comp_idx[l * KK + mt * 128 + tid];
    __syncthreads();

    const __half *pa_hi[2], *pa_lo[2], *pb_hi[2], *pb_lo[2];
    uint32_t sdst[2];
#pragma unroll
    for (int q = 0; q < 2; q++) {
        const int c   = tid + q * 256;
        const int row = c >> 2, ch = c & 3;
        const size_t aoff = ((size_t)l * TT + rows_s[row]) * DD + ch * 8;
        pa_hi[q] = g_hid_hi + aoff;
        pa_lo[q] = g_hid_lo + aoff;
        const size_t boff = ((size_t)l * DD + nt * 128 + row) * DD + ch * 8;
        pb_hi[q] = g_wt_hi + boff;
        pb_lo[q] = g_wt_lo + boff;
        sdst[q] = (uint32_t)(row * ROWB + ch * 16);
    }

    auto load_stage = [&](int buf, int it) {
        const uint32_t base = sb + 1024 + buf * STAGEB;
        const int ko = it * 32;
#pragma unroll
        for (int q = 0; q < 2; q++) {
            cp16(base + 0 * MATB + sdst[q], pa_hi[q] + ko);
            cp16(base + 1 * MATB + sdst[q], pa_lo[q] + ko);
            cp16(base + 2 * MATB + sdst[q], pb_hi[q] + ko);
            cp16(base + 3 * MATB + sdst[q], pb_lo[q] + ko);
        }
        CP_COMMIT();
    };

    const int warp_m = wid & 1;
    const int warp_n = wid >> 1;
    const uint32_t offA = (uint32_t)((warp_m * 64 + (lane & 15)) * ROWB +
                                     ((lane & 16) ? 16 : 0));
    const uint32_t offB = (uint32_t)((warp_n * 32 + (lane & 7) + ((lane & 16) ? 8 : 0)) * ROWB +
                                     ((lane & 8) ? 16 : 0));

    float acc[4][4][4];
#pragma unroll
    for (int i = 0; i < 4; i++)
#pragma unroll
        for (int j = 0; j < 4; j++)
#pragma unroll
            for (int k = 0; k < 4; k++) acc[i][j][k] = 0.f;

    load_stage(0, 0);
    load_stage(1, 1);

    const int NIT = DD / 32;
    int slot = 0;
    for (int it = 0; it < NIT; it++) {
        if (it + 1 < NIT) { CP_WAIT(1); } else { CP_WAIT(0); }
        __syncthreads();
        if (it + 2 < NIT) {
            int ns = slot + 2; if (ns >= 3) ns -= 3;
            load_stage(ns, it + 2);
        }
        const uint32_t base = sb + 1024 + slot * STAGEB;
        const uint32_t Ah = base + 0 * MATB, Al = base + 1 * MATB;
        const uint32_t Bh = base + 2 * MATB, Bl = base + 3 * MATB;
#pragma unroll
        for (int kk = 0; kk < 2; kk++) {
            const uint32_t kof = kk * 32;
            uint32_t ah[4][4], al[4][4], bh[2][4], bl[2][4];
#pragma unroll
            for (int mf = 0; mf < 4; mf++) {
                const uint32_t o = offA + mf * 16 * ROWB + kof;
                ldsm4(ah[mf], Ah + o);
                ldsm4(al[mf], Al + o);
            }
#pragma unroll
            for (int nf2 = 0; nf2 < 2; nf2++) {
                const uint32_t o = offB + nf2 * 16 * ROWB + kof;
                ldsm4(bh[nf2], Bh + o);
                ldsm4(bl[nf2], Bl + o);
            }
#pragma unroll
            for (int mf = 0; mf < 4; mf++) {
#pragma unroll
                for (int nf = 0; nf < 4; nf++) {
                    const int n2 = nf >> 1, s = (nf & 1) * 2;
                    mma_fp16(acc[mf][nf], ah[mf], bh[n2][s], bh[n2][s + 1]);
                    mma_fp16(acc[mf][nf], ah[mf], bl[n2][s], bl[n2][s + 1]);
                    mma_fp16(acc[mf][nf], al[mf], bh[n2][s], bh[n2][s + 1]);
                }
            }
        }
        if (++slot == 3) slot = 0;
    }

    const int g   = lane >> 2;
    const int tig = lane & 3;
#pragma unroll
    for (int mf = 0; mf < 4; mf++) {
        const int m0 = warp_m * 64 + mf * 16 + g;
        const int r0 = rows_s[m0];
        const int r1 = rows_s[m0 + 8];
        float* d0 = out + ((size_t)l * TT + r0) * DD;
        float* d1 = out + ((size_t)l * TT + r1) * DD;
#pragma unroll
        for (int nf = 0; nf < 4; nf++) {
            const int n = nt * 128 + warp_n * 32 + nf * 8 + tig * 2;
            const float2 bv = *(const float2*)(bs1 + l * DD + n);
            float2 o0, o1;
            o0.x = acc[mf][nf][0] + bv.x; o0.y = acc[mf][nf][1] + bv.y;
            o1.x = acc[mf][nf][2] + bv.x; o1.y = acc[mf][nf][3] + bv.y;
            *(float2*)(d0 + n) = o0;
            *(float2*)(d1 + n) = o1;
        }
    }
}

// =================================================================================
extern "C" void kernel_launch(void* const* d_in, const int* in_sizes, int n_in,
                              void* d_out, int out_size) {
    const float* hidden = (const float*)d_in[0];
    const float* s2     = (const float*)d_in[1];
    const float* W_r1   = (const float*)d_in[2];
    const float* b_r1   = (const float*)d_in[3];
    const float* W_r2   = (const float*)d_in[4];
    const float* b_r2   = (const float*)d_in[5];
    const float* W_s1   = (const float*)d_in[6];
    const float* b_s1   = (const float*)d_in[7];
    float* out = (float*)d_out;

    static cudaStream_t sB = nullptr;
    static cudaEvent_t e0, eB, eT, eC;
    static bool init_done = false;
    if (!init_done) {
        cudaFuncSetAttribute(s1_mma_kernel,
                             cudaFuncAttributeMaxDynamicSharedMemorySize, S1_SMEM);
        cudaFuncSetAttribute(router_mma_kernel,
                             cudaFuncAttributeMaxDynamicSharedMemorySize, S1_SMEM);
        cudaStreamCreateWithFlags(&sB, cudaStreamNonBlocking);
        cudaEventCreateWithFlags(&e0, cudaEventDisableTiming);
        cudaEventCreateWithFlags(&eB, cudaEventDisableTiming);
        cudaEventCreateWithFlags(&eT, cudaEventDisableTiming);
        cudaEventCreateWithFlags(&eC, cudaEventDisableTiming);
        init_done = true;
    }

    // main stream: hidden split (needed by both branches)
    conv_hidden_kernel<<<(LL * TT * (DD / 4)) / 256, 256>>>(hidden);
    cudaEventRecord(e0, 0);

    // branch B: W_s1 transpose+split (only needed by s1)
    cudaStreamWaitEvent(sB, e0, 0);
    conv_wt_kernel<<<dim3(DD / 32, DD / 32, LL), dim3(32, 8), 0, sB>>>(W_s1);
    cudaEventRecord(eB, sB);

    // main stream: router chain
    conv_wr1_kernel<<<dim3(RR / 32, DD / 32, LL), dim3(32, 8)>>>(W_r1);
    router_mma_kernel<<<dim3(TT / 128, LL), 256, S1_SMEM>>>(b_r1);
    logits_kernel<<<(LL * TT) / 8, 256>>>(W_r2, b_r2);
    topk_kernel<<<LL, 1024>>>();
    cudaEventRecord(eT, 0);

    // branch B: copy top-K rows (needs topk only), overlapped with s1
    cudaStreamWaitEvent(sB, eT, 0);
    copy_s2_kernel<<<dim3(KK, LL), 256, 0, sB>>>(s2, out);
    cudaEventRecord(eC, sB);

    // main stream: s1 GEMM (needs conv_wt + topk)
    cudaStreamWaitEvent(0, eB, 0);
    dim3 g2(DD / 128, KK / 128, LL);
    s1_mma_kernel<<<g2, 256, S1_SMEM>>>(b_s1, out);
    cudaStreamWaitEvent(0, eC, 0);   // join copy branch
}